// round 1
// baseline (speedup 1.0000x reference)
#include <cuda_runtime.h>
#include <math.h>

#define BN 8192
#define DD 128
#define NT (BN/128)                 // 64 tiles per dim
#define NBLK (NT*(NT+1)/2)          // 2080 triangular tiles
#define MROWS 64                    // rows per MLP block

// -log(1.01f): exact value of the reference's per-pair term when exp(-dist)
// underflows below half-ulp of 1.01f (dist > ~16.6; we use threshold 18).
#define FARV (-0.00995033085316808285f)

// Scratch (device globals: no allocations allowed)
__device__ float  g_h[BN*DD];
__device__ float  g_sq[BN];
__device__ double g_loss;
__device__ double g_hsum;

__global__ void k_init() { g_loss = 0.0; g_hsum = 0.0; }

// ---------------------------------------------------------------------------
// MLP: h = relu(relu(X@W1+b1)@W2+b2)@W3+b3, plus sq[i]=|h_i|^2 and sum(h^2)
// ---------------------------------------------------------------------------

// W stored transposed in smem with 16B group padding every 8 rows so that
// float4 column reads are phase-conflict-free.
__device__ __forceinline__ int wg_addr(int c, int k) {
    return (c >> 3) * (8*DD + 4) + (c & 7) * DD + k;
}

__device__ __forceinline__ void load_w(const float* __restrict__ W, float* Wg) {
    int tid = threadIdx.x;
    for (int e = tid; e < DD*DD/4; e += 256) {
        int k  = e >> 5;      // W row
        int c4 = e & 31;      // float4 column index
        float4 w = *(const float4*)(W + k*DD + c4*4);
        Wg[wg_addr(c4*4+0, k)] = w.x;
        Wg[wg_addr(c4*4+1, k)] = w.y;
        Wg[wg_addr(c4*4+2, k)] = w.z;
        Wg[wg_addr(c4*4+3, k)] = w.w;
    }
}

template<bool RELU>
__device__ __forceinline__ void layer_compute(const float* in, const float* Wg,
                                              const float* bias, float* out) {
    int tid = threadIdx.x;
    int tj = tid & 15, ti = tid >> 4;
    int i0 = ti * 4, j0 = tj * 8;
    float acc[4][8];
    #pragma unroll
    for (int j = 0; j < 8; j++) {
        float bv = bias[j0 + j];
        #pragma unroll
        for (int i = 0; i < 4; i++) acc[i][j] = bv;
    }
    #pragma unroll 1
    for (int kb = 0; kb < DD/4; kb++) {
        float4 a[4], b[8];
        #pragma unroll
        for (int i = 0; i < 4; i++)
            a[i] = *(const float4*)(in + (i0+i)*DD + kb*4);
        #pragma unroll
        for (int j = 0; j < 8; j++)
            b[j] = *(const float4*)(Wg + wg_addr(j0+j, kb*4));
        #pragma unroll
        for (int i = 0; i < 4; i++)
            #pragma unroll
            for (int j = 0; j < 8; j++) {
                acc[i][j] += a[i].x*b[j].x;
                acc[i][j] += a[i].y*b[j].y;
                acc[i][j] += a[i].z*b[j].z;
                acc[i][j] += a[i].w*b[j].w;
            }
    }
    #pragma unroll
    for (int i = 0; i < 4; i++)
        #pragma unroll
        for (int j = 0; j < 8; j++) {
            float v = acc[i][j];
            if (RELU) v = fmaxf(v, 0.0f);
            out[(i0+i)*DD + j0 + j] = v;
        }
}

// smem floats: Wg 16*1028 | actA 64*128 | actB 64*128 | bias 128 | red 8
#define MLP_SMEM ((16*(8*DD+4) + MROWS*DD*2 + DD + 8) * 4)

__global__ void __launch_bounds__(256, 1)
k_mlp(const float* __restrict__ X,
      const float* __restrict__ W1, const float* __restrict__ b1,
      const float* __restrict__ W2, const float* __restrict__ b2,
      const float* __restrict__ W3, const float* __restrict__ b3) {
    extern __shared__ float sm[];
    float* Wg   = sm;
    float* actA = Wg + 16*(8*DD+4);
    float* actB = actA + MROWS*DD;
    float* bias = actB + MROWS*DD;
    float* red  = bias + DD;

    int tid = threadIdx.x;
    int r0  = blockIdx.x * MROWS;

    // load X tile (coalesced)
    for (int e = tid; e < MROWS*DD/4; e += 256)
        ((float4*)actA)[e] = ((const float4*)(X + r0*DD))[e];

    load_w(W1, Wg);
    if (tid < DD) bias[tid] = b1[tid];
    __syncthreads();
    layer_compute<true>(actA, Wg, bias, actB);
    __syncthreads();

    load_w(W2, Wg);
    if (tid < DD) bias[tid] = b2[tid];
    __syncthreads();
    layer_compute<true>(actB, Wg, bias, actA);
    __syncthreads();

    load_w(W3, Wg);
    if (tid < DD) bias[tid] = b3[tid];
    __syncthreads();
    layer_compute<false>(actA, Wg, bias, actB);
    __syncthreads();

    // write h tile to global
    for (int e = tid; e < MROWS*DD/4; e += 256)
        ((float4*)(g_h + r0*DD))[e] = ((float4*)actB)[e];

    // per-row squared norms + global sum(h^2)
    int r = tid >> 2, q = tid & 3;
    float s = 0.0f;
    #pragma unroll
    for (int m = 0; m < 8; m++) {
        float4 v = *(const float4*)(actB + r*DD + q*32 + m*4);
        s += v.x*v.x + v.y*v.y + v.z*v.z + v.w*v.w;
    }
    s += __shfl_xor_sync(0xffffffffu, s, 1);
    s += __shfl_xor_sync(0xffffffffu, s, 2);
    if (q == 0) g_sq[r0 + r] = s;          // full row sum after xor1,2
    s += __shfl_xor_sync(0xffffffffu, s, 4);
    s += __shfl_xor_sync(0xffffffffu, s, 8);
    s += __shfl_xor_sync(0xffffffffu, s, 16);
    if ((tid & 31) == 0) red[tid >> 5] = s;
    __syncthreads();
    if (tid == 0) {
        float tot = 0.0f;
        for (int w = 0; w < 8; w++) tot += red[w];
        atomicAdd(&g_hsum, (double)tot);
    }
}

// ---------------------------------------------------------------------------
// Pairwise: fused G = h h^T (128x128 tiles, upper triangle) + loss reduction
// ---------------------------------------------------------------------------

// smem floats: Hi 128*128 | Hj 128*128 | sqi 128 | sqj 128 | red 8 | yi/yj 2*128 ints
#define PAIR_SMEM ((128*DD*2 + 128*2 + 8) * 4 + 128*2*4)

__global__ void __launch_bounds__(256, 1)
k_pair(const int* __restrict__ y) {
    extern __shared__ float sm[];
    float* Hi  = sm;
    float* Hj  = Hi + 128*DD;
    float* sqi = Hj + 128*DD;
    float* sqj = sqi + 128;
    float* red = sqj + 128;
    int*   yi  = (int*)(red + 8);
    int*   yj  = yi + 128;

    // triangular tile mapping: block t -> (bi, bj) with bi <= bj
    int t = blockIdx.x;
    float nf = (float)NT + 0.5f;
    int bi = (int)(nf - sqrtf(nf*nf - 2.0f*(float)t));
    if (bi < 0) bi = 0;
    if (bi >= NT) bi = NT - 1;
    while (bi*NT - (bi*(bi-1))/2 > t) bi--;
    while ((bi+1)*NT - ((bi+1)*bi)/2 <= t) bi++;
    int bj = bi + (t - (bi*NT - (bi*(bi-1))/2));

    int ri = bi * 128, rj = bj * 128;
    int tid = threadIdx.x;

    for (int e = tid; e < 128*32; e += 256) {
        ((float4*)Hi)[e] = ((const float4*)(g_h + ri*DD))[e];
        ((float4*)Hj)[e] = ((const float4*)(g_h + rj*DD))[e];
    }
    if (tid < 128) {
        sqi[tid] = g_sq[ri + tid];
        sqj[tid] = g_sq[rj + tid];
        yi[tid]  = y[ri + tid];
        yj[tid]  = y[rj + tid];
    }
    __syncthreads();

    int tj = tid & 15, ti = tid >> 4;
    int i0 = ti * 8, j0 = tj * 8;

    float acc[8][8];
    #pragma unroll
    for (int i = 0; i < 8; i++)
        #pragma unroll
        for (int j = 0; j < 8; j++) acc[i][j] = 0.0f;

    #pragma unroll 1
    for (int kb = 0; kb < DD/4; kb++) {
        float4 a[8], b[8];
        #pragma unroll
        for (int i = 0; i < 8; i++)
            a[i] = ((const float4*)Hi)[(i0+i)*32 + kb];
        #pragma unroll
        for (int j = 0; j < 8; j++)
            b[j] = ((const float4*)Hj)[(j0+j)*32 + kb];
        #pragma unroll
        for (int i = 0; i < 8; i++)
            #pragma unroll
            for (int j = 0; j < 8; j++) {
                acc[i][j] += a[i].x*b[j].x;
                acc[i][j] += a[i].y*b[j].y;
                acc[i][j] += a[i].z*b[j].z;
                acc[i][j] += a[i].w*b[j].w;
            }
    }

    // fused loss epilogue
    float si[8], sj8[8];
    int   li[8], lj[8];
    #pragma unroll
    for (int r = 0; r < 8; r++) {
        si[r]  = sqi[i0 + r];  li[r] = yi[i0 + r];
        sj8[r] = sqj[j0 + r];  lj[r] = yj[j0 + r];
    }
    float lsum = 0.0f;
    #pragma unroll
    for (int i = 0; i < 8; i++)
        #pragma unroll
        for (int j = 0; j < 8; j++) {
            float dist = fmaxf(si[i] + sj8[j] - 2.0f*acc[i][j], 0.0f);
            float term;
            if (li[i] != lj[j]) {
                // far branch is bit-equivalent to reference (exp underflows
                // below half-ulp of 1.01f for dist > ~16.6)
                term = (dist < 18.0f) ? (-logf(1.01f - expf(-dist))) : FARV;
            } else {
                term = dist;
            }
            lsum += term;
        }

    lsum += __shfl_xor_sync(0xffffffffu, lsum, 1);
    lsum += __shfl_xor_sync(0xffffffffu, lsum, 2);
    lsum += __shfl_xor_sync(0xffffffffu, lsum, 4);
    lsum += __shfl_xor_sync(0xffffffffu, lsum, 8);
    lsum += __shfl_xor_sync(0xffffffffu, lsum, 16);
    if ((tid & 31) == 0) red[tid >> 5] = lsum;
    __syncthreads();
    if (tid == 0) {
        double tot = 0.0;
        for (int w = 0; w < 8; w++) tot += (double)red[w];
        if (bi != bj) tot *= 2.0;   // off-diagonal tile counts for (i,j) and (j,i)
        atomicAdd(&g_loss, tot);
    }
}

__global__ void k_fin(float* out) {
    double loss = g_loss / ((double)BN * (double)BN);
    loss += 0.01 * (g_hsum / ((double)BN * (double)DD));
    out[0] = (float)loss;
}

// ---------------------------------------------------------------------------

extern "C" void kernel_launch(void* const* d_in, const int* in_sizes, int n_in,
                              void* d_out, int out_size) {
    (void)in_sizes; (void)n_in; (void)out_size;
    const float* X  = (const float*)d_in[0];
    const float* W1 = (const float*)d_in[1];
    const float* b1 = (const float*)d_in[2];
    const float* W2 = (const float*)d_in[3];
    const float* b2 = (const float*)d_in[4];
    const float* W3 = (const float*)d_in[5];
    const float* b3 = (const float*)d_in[6];
    const int*   y  = (const int*)d_in[7];

    cudaFuncSetAttribute(k_mlp,  cudaFuncAttributeMaxDynamicSharedMemorySize, MLP_SMEM);
    cudaFuncSetAttribute(k_pair, cudaFuncAttributeMaxDynamicSharedMemorySize, PAIR_SMEM);

    k_init<<<1, 1>>>();
    k_mlp<<<BN/MROWS, 256, MLP_SMEM>>>(X, W1, b1, W2, b2, W3, b3);
    k_pair<<<NBLK, 256, PAIR_SMEM>>>(y);
    k_fin<<<1, 1>>>((float*)d_out);
}

// round 2
// speedup vs baseline: 1.7336x; 1.7336x over previous
#include <cuda_runtime.h>
#include <math.h>

#define BN 8192
#define DD 128
#define NT (BN/128)                 // 64 tiles per dim
#define NBLK (NT*(NT+1)/2)          // 2080 triangular tiles
#define MROWS 64                    // rows per MLP block
#define HS 33                       // padded row stride in float4 (132 floats)

// -log(1.01f): exact value of the reference's per-pair term when exp(-dist)
// underflows below half-ulp of 1.01f (dist > ~16.6; we use threshold 18).
#define FARV (-0.00995033085316808285f)

// Scratch (device globals: no allocations allowed)
__device__ float  g_h[BN*DD];
__device__ float  g_sq[BN];
__device__ double g_loss;
__device__ double g_hsum;

__global__ void k_init() { g_loss = 0.0; g_hsum = 0.0; }

// ---- packed f32x2 helpers ----
__device__ __forceinline__ unsigned long long pk2(float lo, float hi) {
    unsigned long long r;
    asm("mov.b64 %0, {%1, %2};" : "=l"(r) : "f"(lo), "f"(hi));
    return r;
}
__device__ __forceinline__ void upk2(float& lo, float& hi, unsigned long long v) {
    asm("mov.b64 {%0, %1}, %2;" : "=f"(lo), "=f"(hi) : "l"(v));
}
__device__ __forceinline__ void fma2(unsigned long long& d,
                                     unsigned long long a, unsigned long long b) {
    asm("fma.rn.f32x2 %0, %1, %2, %0;" : "+l"(d) : "l"(a), "l"(b));
}

// ---------------------------------------------------------------------------
// MLP: h = relu(relu(X@W1+b1)@W2+b2)@W3+b3, plus sq[i]=|h_i|^2 and sum(h^2)
// ---------------------------------------------------------------------------

__device__ __forceinline__ int wg_addr(int c, int k) {
    return (c >> 3) * (8*DD + 4) + (c & 7) * DD + k;
}

__device__ __forceinline__ void load_w(const float* __restrict__ W, float* Wg) {
    int tid = threadIdx.x;
    for (int e = tid; e < DD*DD/4; e += 256) {
        int k  = e >> 5;
        int c4 = e & 31;
        float4 w = *(const float4*)(W + k*DD + c4*4);
        Wg[wg_addr(c4*4+0, k)] = w.x;
        Wg[wg_addr(c4*4+1, k)] = w.y;
        Wg[wg_addr(c4*4+2, k)] = w.z;
        Wg[wg_addr(c4*4+3, k)] = w.w;
    }
}

template<bool RELU>
__device__ __forceinline__ void layer_compute(const float* in, const float* Wg,
                                              const float* bias, float* out) {
    int tid = threadIdx.x;
    int tj = tid & 15, ti = tid >> 4;
    int i0 = ti * 4, j0 = tj * 8;
    float acc[4][8];
    #pragma unroll
    for (int j = 0; j < 8; j++) {
        float bv = bias[j0 + j];
        #pragma unroll
        for (int i = 0; i < 4; i++) acc[i][j] = bv;
    }
    #pragma unroll 1
    for (int kb = 0; kb < DD/4; kb++) {
        float4 a[4], b[8];
        #pragma unroll
        for (int i = 0; i < 4; i++)
            a[i] = *(const float4*)(in + (i0+i)*DD + kb*4);
        #pragma unroll
        for (int j = 0; j < 8; j++)
            b[j] = *(const float4*)(Wg + wg_addr(j0+j, kb*4));
        #pragma unroll
        for (int i = 0; i < 4; i++)
            #pragma unroll
            for (int j = 0; j < 8; j++) {
                acc[i][j] += a[i].x*b[j].x;
                acc[i][j] += a[i].y*b[j].y;
                acc[i][j] += a[i].z*b[j].z;
                acc[i][j] += a[i].w*b[j].w;
            }
    }
    #pragma unroll
    for (int i = 0; i < 4; i++)
        #pragma unroll
        for (int j = 0; j < 8; j++) {
            float v = acc[i][j];
            if (RELU) v = fmaxf(v, 0.0f);
            out[(i0+i)*DD + j0 + j] = v;
        }
}

#define MLP_SMEM ((16*(8*DD+4) + MROWS*DD*2 + DD + 8) * 4)

__global__ void __launch_bounds__(256, 1)
k_mlp(const float* __restrict__ X,
      const float* __restrict__ W1, const float* __restrict__ b1,
      const float* __restrict__ W2, const float* __restrict__ b2,
      const float* __restrict__ W3, const float* __restrict__ b3) {
    extern __shared__ float sm[];
    float* Wg   = sm;
    float* actA = Wg + 16*(8*DD+4);
    float* actB = actA + MROWS*DD;
    float* bias = actB + MROWS*DD;
    float* red  = bias + DD;

    int tid = threadIdx.x;
    int r0  = blockIdx.x * MROWS;

    for (int e = tid; e < MROWS*DD/4; e += 256)
        ((float4*)actA)[e] = ((const float4*)(X + r0*DD))[e];

    load_w(W1, Wg);
    if (tid < DD) bias[tid] = b1[tid];
    __syncthreads();
    layer_compute<true>(actA, Wg, bias, actB);
    __syncthreads();

    load_w(W2, Wg);
    if (tid < DD) bias[tid] = b2[tid];
    __syncthreads();
    layer_compute<true>(actB, Wg, bias, actA);
    __syncthreads();

    load_w(W3, Wg);
    if (tid < DD) bias[tid] = b3[tid];
    __syncthreads();
    layer_compute<false>(actA, Wg, bias, actB);
    __syncthreads();

    for (int e = tid; e < MROWS*DD/4; e += 256)
        ((float4*)(g_h + r0*DD))[e] = ((float4*)actB)[e];

    int r = tid >> 2, q = tid & 3;
    float s = 0.0f;
    #pragma unroll
    for (int m = 0; m < 8; m++) {
        float4 v = *(const float4*)(actB + r*DD + q*32 + m*4);
        s += v.x*v.x + v.y*v.y + v.z*v.z + v.w*v.w;
    }
    s += __shfl_xor_sync(0xffffffffu, s, 1);
    s += __shfl_xor_sync(0xffffffffu, s, 2);
    if (q == 0) g_sq[r0 + r] = s;
    s += __shfl_xor_sync(0xffffffffu, s, 4);
    s += __shfl_xor_sync(0xffffffffu, s, 8);
    s += __shfl_xor_sync(0xffffffffu, s, 16);
    if ((tid & 31) == 0) red[tid >> 5] = s;
    __syncthreads();
    if (tid == 0) {
        float tot = 0.0f;
        for (int w = 0; w < 8; w++) tot += red[w];
        atomicAdd(&g_hsum, (double)tot);
    }
}

// ---------------------------------------------------------------------------
// Pairwise: fused G = h h^T (128x128 tiles, upper triangle) + loss reduction
// Packed fma.rn.f32x2 math; Hj columns mapped strided (tj + 16*j) so b-loads
// hit banks {0,4,...,28} within each 8-lane LDS.128 phase (conflict-free).
// ---------------------------------------------------------------------------

// smem floats: Hi 128*132 | Hj 128*132 | sqi 128 | sqj 128 | red 8 | yi/yj ints
#define PAIR_SMEM ((128*HS*4*2 + 128*2 + 8) * 4 + 128*2*4)

__global__ void __launch_bounds__(256, 1)
k_pair(const int* __restrict__ y) {
    extern __shared__ float sm[];
    float* Hi  = sm;
    float* Hj  = Hi + 128*HS*4;
    float* sqi = Hj + 128*HS*4;
    float* sqj = sqi + 128;
    float* red = sqj + 128;
    int*   yi  = (int*)(red + 8);
    int*   yj  = yi + 128;

    // triangular tile mapping: block t -> (bi, bj) with bi <= bj
    int t = blockIdx.x;
    float nf = (float)NT + 0.5f;
    int bi = (int)(nf - sqrtf(nf*nf - 2.0f*(float)t));
    if (bi < 0) bi = 0;
    if (bi >= NT) bi = NT - 1;
    while (bi*NT - (bi*(bi-1))/2 > t) bi--;
    while ((bi+1)*NT - ((bi+1)*bi)/2 <= t) bi++;
    int bj = bi + (t - (bi*NT - (bi*(bi-1))/2));

    int ri = bi * 128, rj = bj * 128;
    int tid = threadIdx.x;

    for (int e = tid; e < 128*32; e += 256) {
        int r = e >> 5, c = e & 31;
        ((float4*)Hi)[r*HS + c] = ((const float4*)(g_h + ri*DD))[e];
        ((float4*)Hj)[r*HS + c] = ((const float4*)(g_h + rj*DD))[e];
    }
    if (tid < 128) {
        sqi[tid] = g_sq[ri + tid];
        sqj[tid] = g_sq[rj + tid];
        yi[tid]  = y[ri + tid];
        yj[tid]  = y[rj + tid];
    }
    __syncthreads();

    int tj = tid & 15, ti = tid >> 4;
    int i0 = ti * 8;
    // thread's 8 columns: tj + 16*j, j = 0..7; packed pairs p: (tj+32p, tj+32p+16)

    unsigned long long acc[8][4];
    #pragma unroll
    for (int i = 0; i < 8; i++)
        #pragma unroll
        for (int p = 0; p < 4; p++) acc[i][p] = 0ULL;

    #pragma unroll 1
    for (int kb = 0; kb < DD/4; kb++) {
        float4 a4[8], b4[8];
        #pragma unroll
        for (int i = 0; i < 8; i++)
            a4[i] = ((const float4*)Hi)[(i0+i)*HS + kb];
        #pragma unroll
        for (int j = 0; j < 8; j++)
            b4[j] = ((const float4*)Hj)[(tj + j*16)*HS + kb];

        #define PW_STEP(C)                                                  \
        {                                                                   \
            unsigned long long bp[4];                                       \
            _Pragma("unroll")                                               \
            for (int p = 0; p < 4; p++)                                     \
                bp[p] = pk2(b4[2*p].C, b4[2*p+1].C);                        \
            _Pragma("unroll")                                               \
            for (int i = 0; i < 8; i++) {                                   \
                unsigned long long ad = pk2(a4[i].C, a4[i].C);              \
                _Pragma("unroll")                                           \
                for (int p = 0; p < 4; p++)                                 \
                    fma2(acc[i][p], ad, bp[p]);                             \
            }                                                               \
        }
        PW_STEP(x)
        PW_STEP(y)
        PW_STEP(z)
        PW_STEP(w)
        #undef PW_STEP
    }

    // fused loss epilogue
    float lsum = 0.0f;
    #pragma unroll
    for (int i = 0; i < 8; i++) {
        float si = sqi[i0 + i];
        int   li = yi[i0 + i];
        #pragma unroll
        for (int p = 0; p < 4; p++) {
            int cA = tj + p*32;
            int cB = cA + 16;
            float dA, dB;
            upk2(dA, dB, acc[i][p]);
            {
                float dist = fmaxf(si + sqj[cA] - 2.0f*dA, 0.0f);
                float term;
                if (li != yj[cA])
                    term = (dist < 18.0f) ? (-logf(1.01f - expf(-dist))) : FARV;
                else
                    term = dist;
                lsum += term;
            }
            {
                float dist = fmaxf(si + sqj[cB] - 2.0f*dB, 0.0f);
                float term;
                if (li != yj[cB])
                    term = (dist < 18.0f) ? (-logf(1.01f - expf(-dist))) : FARV;
                else
                    term = dist;
                lsum += term;
            }
        }
    }

    lsum += __shfl_xor_sync(0xffffffffu, lsum, 1);
    lsum += __shfl_xor_sync(0xffffffffu, lsum, 2);
    lsum += __shfl_xor_sync(0xffffffffu, lsum, 4);
    lsum += __shfl_xor_sync(0xffffffffu, lsum, 8);
    lsum += __shfl_xor_sync(0xffffffffu, lsum, 16);
    if ((tid & 31) == 0) red[tid >> 5] = lsum;
    __syncthreads();
    if (tid == 0) {
        double tot = 0.0;
        for (int w = 0; w < 8; w++) tot += (double)red[w];
        if (bi != bj) tot *= 2.0;
        atomicAdd(&g_loss, tot);
    }
}

__global__ void k_fin(float* out) {
    double loss = g_loss / ((double)BN * (double)BN);
    loss += 0.01 * (g_hsum / ((double)BN * (double)DD));
    out[0] = (float)loss;
}

// ---------------------------------------------------------------------------

extern "C" void kernel_launch(void* const* d_in, const int* in_sizes, int n_in,
                              void* d_out, int out_size) {
    (void)in_sizes; (void)n_in; (void)out_size;
    const float* X  = (const float*)d_in[0];
    const float* W1 = (const float*)d_in[1];
    const float* b1 = (const float*)d_in[2];
    const float* W2 = (const float*)d_in[3];
    const float* b2 = (const float*)d_in[4];
    const float* W3 = (const float*)d_in[5];
    const float* b3 = (const float*)d_in[6];
    const int*   y  = (const int*)d_in[7];

    cudaFuncSetAttribute(k_mlp,  cudaFuncAttributeMaxDynamicSharedMemorySize, MLP_SMEM);
    cudaFuncSetAttribute(k_pair, cudaFuncAttributeMaxDynamicSharedMemorySize, PAIR_SMEM);

    k_init<<<1, 1>>>();
    k_mlp<<<BN/MROWS, 256, MLP_SMEM>>>(X, W1, b1, W2, b2, W3, b3);
    k_pair<<<NBLK, 256, PAIR_SMEM>>>(y);
    k_fin<<<1, 1>>>((float*)d_out);
}

// round 4
// speedup vs baseline: 5.9026x; 3.4048x over previous
#include <cuda_runtime.h>
#include <cuda_bf16.h>
#include <math.h>
#include <cstdint>

#define BN 8192
#define DD 128
#define NT (BN/128)                 // 64 tiles per dim
#define NBLK (NT*(NT+1)/2)          // 2080 triangular tiles
#define MROWS 64                    // rows per MLP block

// -log(1.01f): exact value of the reference's per-pair term when exp(-dist)
// underflows below half-ulp of 1.01f (dist > ~16.6; we use threshold 18).
#define FARV (-0.00995033085316808285f)

// Scratch (device globals: no allocations allowed)
__device__ __nv_bfloat16 g_h[BN*DD];   // bf16-rounded h
__device__ float  g_sq[BN];            // |h~|^2 from ROUNDED values
__device__ double g_loss;
__device__ double g_hsum;

__global__ void k_init() { g_loss = 0.0; g_hsum = 0.0; }

// ---------------- warp-MMA helpers (plain sm_80+ PTX, no 'a' features) -----
__device__ __forceinline__ void ldm_x4(uint32_t& r0, uint32_t& r1,
                                       uint32_t& r2, uint32_t& r3, uint32_t addr) {
    asm volatile("ldmatrix.sync.aligned.m8n8.x4.shared.b16 {%0,%1,%2,%3}, [%4];"
                 : "=r"(r0), "=r"(r1), "=r"(r2), "=r"(r3) : "r"(addr));
}
__device__ __forceinline__ void mma_bf16(float* d, const uint32_t* a, const uint32_t* b) {
    asm volatile("mma.sync.aligned.m16n8k16.row.col.f32.bf16.bf16.f32 "
                 "{%0,%1,%2,%3}, {%4,%5,%6,%7}, {%8,%9}, {%0,%1,%2,%3};"
                 : "+f"(d[0]), "+f"(d[1]), "+f"(d[2]), "+f"(d[3])
                 : "r"(a[0]), "r"(a[1]), "r"(a[2]), "r"(a[3]), "r"(b[0]), "r"(b[1]));
}
__device__ __forceinline__ uint32_t smem_to_u32(const void* p) {
    uint32_t a;
    asm("{ .reg .u64 t; cvta.to.shared.u64 t, %1; cvt.u32.u64 %0, t; }" : "=r"(a) : "l"(p));
    return a;
}

// ---------------------------------------------------------------------------
// MLP: h = relu(relu(X@W1+b1)@W2+b2)@W3+b3 (fp32), round h to bf16 (RN),
// store rounded h; compute sq/sum from the ROUNDED values so that
// dist = |h~i - h~j|^2 is consistent with the bf16 MMA.
// ---------------------------------------------------------------------------

__device__ __forceinline__ int wg_addr(int c, int k) {
    return (c >> 3) * (8*DD + 4) + (c & 7) * DD + k;
}

__device__ __forceinline__ void load_w(const float* __restrict__ W, float* Wg) {
    int tid = threadIdx.x;
    for (int e = tid; e < DD*DD/4; e += 256) {
        int k  = e >> 5;
        int c4 = e & 31;
        float4 w = *(const float4*)(W + k*DD + c4*4);
        Wg[wg_addr(c4*4+0, k)] = w.x;
        Wg[wg_addr(c4*4+1, k)] = w.y;
        Wg[wg_addr(c4*4+2, k)] = w.z;
        Wg[wg_addr(c4*4+3, k)] = w.w;
    }
}

template<bool RELU>
__device__ __forceinline__ void layer_compute(const float* in, const float* Wg,
                                              const float* bias, float* out) {
    int tid = threadIdx.x;
    int tj = tid & 15, ti = tid >> 4;
    int i0 = ti * 4, j0 = tj * 8;
    float acc[4][8];
    #pragma unroll
    for (int j = 0; j < 8; j++) {
        float bv = bias[j0 + j];
        #pragma unroll
        for (int i = 0; i < 4; i++) acc[i][j] = bv;
    }
    #pragma unroll 1
    for (int kb = 0; kb < DD/4; kb++) {
        float4 a[4], b[8];
        #pragma unroll
        for (int i = 0; i < 4; i++)
            a[i] = *(const float4*)(in + (i0+i)*DD + kb*4);
        #pragma unroll
        for (int j = 0; j < 8; j++)
            b[j] = *(const float4*)(Wg + wg_addr(j0+j, kb*4));
        #pragma unroll
        for (int i = 0; i < 4; i++)
            #pragma unroll
            for (int j = 0; j < 8; j++) {
                acc[i][j] += a[i].x*b[j].x;
                acc[i][j] += a[i].y*b[j].y;
                acc[i][j] += a[i].z*b[j].z;
                acc[i][j] += a[i].w*b[j].w;
            }
    }
    #pragma unroll
    for (int i = 0; i < 4; i++)
        #pragma unroll
        for (int j = 0; j < 8; j++) {
            float v = acc[i][j];
            if (RELU) v = fmaxf(v, 0.0f);
            out[(i0+i)*DD + j0 + j] = v;
        }
}

#define MLP_SMEM ((16*(8*DD+4) + MROWS*DD*2 + DD + 8) * 4)

__global__ void __launch_bounds__(256, 1)
k_mlp(const float* __restrict__ X,
      const float* __restrict__ W1, const float* __restrict__ b1,
      const float* __restrict__ W2, const float* __restrict__ b2,
      const float* __restrict__ W3, const float* __restrict__ b3) {
    extern __shared__ float sm[];
    float* Wg   = sm;
    float* actA = Wg + 16*(8*DD+4);
    float* actB = actA + MROWS*DD;
    float* bias = actB + MROWS*DD;
    float* red  = bias + DD;

    int tid = threadIdx.x;
    int r0  = blockIdx.x * MROWS;

    for (int e = tid; e < MROWS*DD/4; e += 256)
        ((float4*)actA)[e] = ((const float4*)(X + r0*DD))[e];

    load_w(W1, Wg);
    if (tid < DD) bias[tid] = b1[tid];
    __syncthreads();
    layer_compute<true>(actA, Wg, bias, actB);
    __syncthreads();

    load_w(W2, Wg);
    if (tid < DD) bias[tid] = b2[tid];
    __syncthreads();
    layer_compute<true>(actB, Wg, bias, actA);
    __syncthreads();

    load_w(W3, Wg);
    if (tid < DD) bias[tid] = b3[tid];
    __syncthreads();
    layer_compute<false>(actA, Wg, bias, actB);
    __syncthreads();

    // round to bf16 (RN): store packed bf16 to gmem, rounded fp32 back to smem
    for (int e = tid; e < MROWS*DD/4; e += 256) {
        float4 v = ((float4*)actB)[e];
        __nv_bfloat162 p0 = __float22bfloat162_rn(make_float2(v.x, v.y));
        __nv_bfloat162 p1 = __float22bfloat162_rn(make_float2(v.z, v.w));
        uint2 packed;
        packed.x = *(const uint32_t*)&p0;
        packed.y = *(const uint32_t*)&p1;
        ((uint2*)(g_h + r0*DD))[e] = packed;
        float2 f0 = __bfloat1622float2(p0);
        float2 f1 = __bfloat1622float2(p1);
        v.x = f0.x; v.y = f0.y; v.z = f1.x; v.w = f1.y;
        ((float4*)actB)[e] = v;
    }
    __syncthreads();

    // per-row squared norms + global sum(h^2), from rounded values
    int r = tid >> 2, q = tid & 3;
    float s = 0.0f;
    #pragma unroll
    for (int m = 0; m < 8; m++) {
        float4 v = *(const float4*)(actB + r*DD + q*32 + m*4);
        s += v.x*v.x + v.y*v.y + v.z*v.z + v.w*v.w;
    }
    s += __shfl_xor_sync(0xffffffffu, s, 1);
    s += __shfl_xor_sync(0xffffffffu, s, 2);
    if (q == 0) g_sq[r0 + r] = s;
    s += __shfl_xor_sync(0xffffffffu, s, 4);
    s += __shfl_xor_sync(0xffffffffu, s, 8);
    s += __shfl_xor_sync(0xffffffffu, s, 16);
    if ((tid & 31) == 0) red[tid >> 5] = s;
    __syncthreads();
    if (tid == 0) {
        float tot = 0.0f;
        for (int w = 0; w < 8; w++) tot += red[w];
        atomicAdd(&g_hsum, (double)tot);
    }
}

// ---------------------------------------------------------------------------
// Pairwise via warp-level bf16 mma.sync (HMMA): one 128x128 tile per CTA.
// SMEM tiles hold bf16 rows of 256B with XOR swizzle: 16B chunk c of row r
// lives at r*256 + ((c ^ (r&7))<<4)  -> ldmatrix and STS.128 conflict-free.
// 8 warps in a 4x2 grid: warp (wr=w&3, wc=w>>2) computes rows wr*32..+31,
// cols wc*64..+63 as 2 m-tiles x 8 n-tiles of m16n8k16, 8 k-steps.
// ---------------------------------------------------------------------------

#define HI_OFF 4096
#define HJ_OFF (4096 + 32768)
#define PAIR_SMEM (4096 + 2*32768)

__global__ void __launch_bounds__(256, 2)
k_pair(const int* __restrict__ y) {
    extern __shared__ char smc[];
    float* redf = (float*)(smc + 16);
    float* sqi  = (float*)(smc + 64);
    float* sqj  = (float*)(smc + 576);
    int*   yi   = (int*)(smc + 1088);
    int*   yj   = (int*)(smc + 1600);
    char*  Hi   = smc + HI_OFF;
    char*  Hj   = smc + HJ_OFF;

    int tid = threadIdx.x, wid = tid >> 5, lane = tid & 31;

    // triangular tile mapping: block t -> (bi, bj) with bi <= bj
    int t = blockIdx.x;
    float nf = (float)NT + 0.5f;
    int bi = (int)(nf - sqrtf(nf*nf - 2.0f*(float)t));
    if (bi < 0) bi = 0;
    if (bi >= NT) bi = NT - 1;
    while (bi*NT - (bi*(bi-1))/2 > t) bi--;
    while ((bi+1)*NT - ((bi+1)*bi)/2 <= t) bi++;
    int bj = bi + (t - (bi*NT - (bi*(bi-1))/2));

    int ri = bi * 128, rj = bj * 128;

    // load bf16 tiles (16B chunks) into swizzled SMEM
    const uint4* gi = (const uint4*)(g_h + ri*DD);
    const uint4* gj = (const uint4*)(g_h + rj*DD);
    for (int e = tid; e < 128*16; e += 256) {
        int r = e >> 4, c = e & 15;
        uint32_t off = (uint32_t)r*256 + (uint32_t)((c ^ (r & 7)) << 4);
        *(uint4*)(Hi + off) = gi[e];
        *(uint4*)(Hj + off) = gj[e];
    }
    if (tid < 128) {
        sqi[tid] = g_sq[ri + tid];
        sqj[tid] = g_sq[rj + tid];
        yi[tid]  = y[ri + tid];
        yj[tid]  = y[rj + tid];
    }
    __syncthreads();

    uint32_t hiB = smem_to_u32(Hi);
    uint32_t hjB = smem_to_u32(Hj);
    int wr = wid & 3, wc = wid >> 2;

    float acc[2][8][4];
    #pragma unroll
    for (int mt = 0; mt < 2; mt++)
        #pragma unroll
        for (int nt = 0; nt < 8; nt++)
            #pragma unroll
            for (int k = 0; k < 4; k++) acc[mt][nt][k] = 0.0f;

    // ldmatrix lane roles
    int aRow0 = wr*32 + (lane & 15);          // + mt*16
    int aSel  = lane >> 4;                    // 0: k-lo chunk, 1: k-hi chunk
    int bg    = lane >> 3;                    // group 0..3
    int bRow0 = wc*64 + ((bg >> 1) << 3) + (lane & 7);  // + np*16
    int bSel  = bg & 1;

    #pragma unroll 1
    for (int ks = 0; ks < 8; ks++) {
        uint32_t a[2][4];
        #pragma unroll
        for (int mt = 0; mt < 2; mt++) {
            int row = aRow0 + mt*16;
            uint32_t addr = hiB + (uint32_t)row*256
                          + (uint32_t)((((ks << 1) | aSel) ^ (row & 7)) << 4);
            ldm_x4(a[mt][0], a[mt][1], a[mt][2], a[mt][3], addr);
        }
        uint32_t b[8][2];
        #pragma unroll
        for (int np = 0; np < 4; np++) {
            int row = bRow0 + np*16;
            uint32_t addr = hjB + (uint32_t)row*256
                          + (uint32_t)((((ks << 1) | bSel) ^ (row & 7)) << 4);
            uint32_t r0, r1, r2, r3;
            ldm_x4(r0, r1, r2, r3, addr);
            b[2*np][0] = r0; b[2*np][1] = r1;
            b[2*np+1][0] = r2; b[2*np+1][1] = r3;
        }
        #pragma unroll
        for (int mt = 0; mt < 2; mt++)
            #pragma unroll
            for (int nt = 0; nt < 8; nt++)
                mma_bf16(acc[mt][nt], a[mt], b[nt]);
    }

    // fused loss epilogue; C frag: (r, c2),(r, c2+1),(r+8, c2),(r+8, c2+1)
    int r8 = lane >> 2, c2 = (lane & 3) << 1;
    float si[2][2]; int li[2][2];
    #pragma unroll
    for (int mt = 0; mt < 2; mt++)
        #pragma unroll
        for (int h = 0; h < 2; h++) {
            int row = wr*32 + mt*16 + h*8 + r8;
            si[mt][h] = sqi[row];
            li[mt][h] = yi[row];
        }
    float sj[8][2]; int lj[8][2];
    #pragma unroll
    for (int nt = 0; nt < 8; nt++)
        #pragma unroll
        for (int q = 0; q < 2; q++) {
            int col = wc*64 + nt*8 + c2 + q;
            sj[nt][q] = sqj[col];
            lj[nt][q] = yj[col];
        }

    float lsum = 0.0f;
    #pragma unroll
    for (int mt = 0; mt < 2; mt++)
        #pragma unroll
        for (int nt = 0; nt < 8; nt++) {
            #pragma unroll
            for (int h = 0; h < 2; h++)
                #pragma unroll
                for (int q = 0; q < 2; q++) {
                    float d = acc[mt][nt][h*2 + q];
                    float dist = fmaxf(si[mt][h] + sj[nt][q] - 2.0f*d, 0.0f);
                    lsum += (li[mt][h] != lj[nt][q])
                          ? ((dist < 18.0f) ? (-logf(1.01f - expf(-dist))) : FARV)
                          : dist;
                }
        }

    lsum += __shfl_xor_sync(0xffffffffu, lsum, 1);
    lsum += __shfl_xor_sync(0xffffffffu, lsum, 2);
    lsum += __shfl_xor_sync(0xffffffffu, lsum, 4);
    lsum += __shfl_xor_sync(0xffffffffu, lsum, 8);
    lsum += __shfl_xor_sync(0xffffffffu, lsum, 16);
    if (lane == 0) redf[wid] = lsum;
    __syncthreads();
    if (tid == 0) {
        double tot = 0.0;
        for (int w = 0; w < 8; w++) tot += (double)redf[w];
        if (bi != bj) tot *= 2.0;
        atomicAdd(&g_loss, tot);
    }
}

__global__ void k_fin(float* out) {
    double loss = g_loss / ((double)BN * (double)BN);
    loss += 0.01 * (g_hsum / ((double)BN * (double)DD));
    out[0] = (float)loss;
}

// ---------------------------------------------------------------------------

extern "C" void kernel_launch(void* const* d_in, const int* in_sizes, int n_in,
                              void* d_out, int out_size) {
    (void)in_sizes; (void)n_in; (void)out_size;
    const float* X  = (const float*)d_in[0];
    const float* W1 = (const float*)d_in[1];
    const float* b1 = (const float*)d_in[2];
    const float* W2 = (const float*)d_in[3];
    const float* b2 = (const float*)d_in[4];
    const float* W3 = (const float*)d_in[5];
    const float* b3 = (const float*)d_in[6];
    const int*   y  = (const int*)d_in[7];

    cudaFuncSetAttribute(k_mlp,  cudaFuncAttributeMaxDynamicSharedMemorySize, MLP_SMEM);
    cudaFuncSetAttribute(k_pair, cudaFuncAttributeMaxDynamicSharedMemorySize, PAIR_SMEM);

    k_init<<<1, 1>>>();
    k_mlp<<<BN/MROWS, 256, MLP_SMEM>>>(X, W1, b1, W2, b2, W3, b3);
    k_pair<<<NBLK, 256, PAIR_SMEM>>>(y);
    k_fin<<<1, 1>>>((float*)d_out);
}

// round 5
// speedup vs baseline: 6.2149x; 1.0529x over previous
#include <cuda_runtime.h>
#include <cuda_bf16.h>
#include <math.h>
#include <cstdint>

#define BN 8192
#define DD 128
#define NT (BN/128)                 // 64 tiles per dim
#define NBLK (NT*(NT+1)/2)          // 2080 triangular tiles

// -log(1.01f): exact value of the reference's per-pair term when exp(-dist)
// underflows below half-ulp of 1.01f (dist > ~16.6; we use threshold 18).
#define FARV (-0.00995033085316808285f)

// Scratch (device globals: no allocations allowed)
// g_h / g_x / g_wt use a "swizzled row" layout: each 128-col bf16 row is 256B,
// split into 16 16B chunks; chunk c of row r lives at byte r*256 + ((c^(r&7))<<4).
// This is exactly the smem layout the ldmatrix code consumes, so gmem<->smem
// tile moves are plain linear copies.
__device__ __nv_bfloat16 g_h[BN*DD];
__device__ __nv_bfloat16 g_x[BN*DD];
__device__ __nv_bfloat16 g_wt[3][DD*DD];   // W transposed: rows = n, cols = k
__device__ float  g_sq[BN];                // |h~|^2 from ROUNDED values
__device__ double g_loss;
__device__ double g_hsum;
__device__ unsigned g_ticket;

// ---------------- warp-MMA helpers (plain sm_80+ PTX, no 'a' features) -----
__device__ __forceinline__ void ldm_x4(uint32_t& r0, uint32_t& r1,
                                       uint32_t& r2, uint32_t& r3, uint32_t addr) {
    asm volatile("ldmatrix.sync.aligned.m8n8.x4.shared.b16 {%0,%1,%2,%3}, [%4];"
                 : "=r"(r0), "=r"(r1), "=r"(r2), "=r"(r3) : "r"(addr));
}
__device__ __forceinline__ void mma_bf16(float* d, const uint32_t* a, const uint32_t* b) {
    asm volatile("mma.sync.aligned.m16n8k16.row.col.f32.bf16.bf16.f32 "
                 "{%0,%1,%2,%3}, {%4,%5,%6,%7}, {%8,%9}, {%0,%1,%2,%3};"
                 : "+f"(d[0]), "+f"(d[1]), "+f"(d[2]), "+f"(d[3])
                 : "r"(a[0]), "r"(a[1]), "r"(a[2]), "r"(a[3]), "r"(b[0]), "r"(b[1]));
}
__device__ __forceinline__ uint32_t smem_to_u32(const void* p) {
    uint32_t a;
    asm("{ .reg .u64 t; cvta.to.shared.u64 t, %1; cvt.u32.u64 %0, t; }" : "=r"(a) : "l"(p));
    return a;
}

// ---------------------------------------------------------------------------
// Prep: round X -> bf16 (swizzled rows), transpose+round W1..3 -> bf16
// (swizzled rows of Wt, row index = n), zero accumulators.
// grid = 3 (W blocks) + 512 (X blocks), 256 threads.
// ---------------------------------------------------------------------------
__global__ void __launch_bounds__(256)
k_prep(const float* __restrict__ X, const float* __restrict__ W1,
       const float* __restrict__ W2, const float* __restrict__ W3) {
    int tid = threadIdx.x, b = blockIdx.x;
    if (b < 3) {
        const float* W = (b == 0) ? W1 : (b == 1) ? W2 : W3;
        uint4* dst = (uint4*)g_wt[b];
        for (int cid = tid; cid < DD*16; cid += 256) {
            int n = cid >> 4, c = cid & 15;
            uint32_t pk[4];
            #pragma unroll
            for (int p = 0; p < 4; p++) {
                float lo = W[(c*8 + 2*p    ) * DD + n];
                float hi = W[(c*8 + 2*p + 1) * DD + n];
                __nv_bfloat162 h2 = __float22bfloat162_rn(make_float2(lo, hi));
                pk[p] = *(const uint32_t*)&h2;
            }
            dst[n*16 + (c ^ (n & 7))] = make_uint4(pk[0], pk[1], pk[2], pk[3]);
        }
        if (b == 0 && tid == 0) { g_loss = 0.0; g_hsum = 0.0; g_ticket = 0u; }
    } else {
        int id  = (b - 3)*256 + tid;     // 16B-chunk id, 0..131071
        int row = id >> 4, c = id & 15;
        const float4* src = (const float4*)X;
        float4 v0 = src[row*32 + c*2];
        float4 v1 = src[row*32 + c*2 + 1];
        __nv_bfloat162 p0 = __float22bfloat162_rn(make_float2(v0.x, v0.y));
        __nv_bfloat162 p1 = __float22bfloat162_rn(make_float2(v0.z, v0.w));
        __nv_bfloat162 p2 = __float22bfloat162_rn(make_float2(v1.x, v1.y));
        __nv_bfloat162 p3 = __float22bfloat162_rn(make_float2(v1.z, v1.w));
        uint4 v = make_uint4(*(const uint32_t*)&p0, *(const uint32_t*)&p1,
                             *(const uint32_t*)&p2, *(const uint32_t*)&p3);
        ((uint4*)g_x)[row*16 + (c ^ (row & 7))] = v;
    }
}

// ---------------------------------------------------------------------------
// Tensor-core MLP: per CTA 64 rows, 8 warps as 2x4 (wr rows, wc cols).
// Each warp: 2 m-tiles x 4 n-tiles x 8 k-steps of m16n8k16 bf16 MMA.
// fp32 accum + fp32 bias, relu (layers 1,2), bf16 RN rounding between layers;
// sq computed from ROUNDED final h.
// ---------------------------------------------------------------------------
#define MLP_A   1024
#define MLP_A2  (1024 + 16384)
#define MLP_W   (1024 + 32768)
#define MLP_SMEM (1024 + 32768 + 32768)

__device__ __forceinline__ void mlp_mma(const char* smc, int aOff, float acc[2][4][4],
                                        int lane, int wr, int wc) {
    uint32_t aB = smem_to_u32(smc + aOff);
    uint32_t wB = smem_to_u32(smc + MLP_W);
    #pragma unroll
    for (int mt = 0; mt < 2; mt++)
        #pragma unroll
        for (int nt = 0; nt < 4; nt++)
            #pragma unroll
            for (int k = 0; k < 4; k++) acc[mt][nt][k] = 0.0f;

    int aRow0 = wr*32 + (lane & 15);
    int aSel  = lane >> 4;
    int bg    = lane >> 3;
    int bRow0 = wc*32 + ((bg >> 1) << 3) + (lane & 7);
    int bSel  = bg & 1;

    #pragma unroll 1
    for (int ks = 0; ks < 8; ks++) {
        uint32_t a[2][4];
        #pragma unroll
        for (int mt = 0; mt < 2; mt++) {
            int row = aRow0 + mt*16;
            uint32_t addr = aB + (uint32_t)row*256
                          + (uint32_t)((((ks << 1) | aSel) ^ (row & 7)) << 4);
            ldm_x4(a[mt][0], a[mt][1], a[mt][2], a[mt][3], addr);
        }
        uint32_t bfr[4][2];
        #pragma unroll
        for (int p = 0; p < 2; p++) {
            int row = bRow0 + p*16;
            uint32_t addr = wB + (uint32_t)row*256
                          + (uint32_t)((((ks << 1) | bSel) ^ (row & 7)) << 4);
            uint32_t r0, r1, r2, r3;
            ldm_x4(r0, r1, r2, r3, addr);
            bfr[2*p][0] = r0; bfr[2*p][1] = r1;
            bfr[2*p+1][0] = r2; bfr[2*p+1][1] = r3;
        }
        #pragma unroll
        for (int mt = 0; mt < 2; mt++)
            #pragma unroll
            for (int nt = 0; nt < 4; nt++)
                mma_bf16(acc[mt][nt], a[mt], bfr[nt]);
    }
}

template<bool RELU, bool LAST>
__device__ __forceinline__ void mlp_store(char* smc, int outOff, float acc[2][4][4],
                                          const float* biasf, float* sq_sm,
                                          int lane, int wr, int wc) {
    int r8 = lane >> 2, c2 = (lane & 3) << 1;
    #pragma unroll
    for (int mt = 0; mt < 2; mt++) {
        float srow[2] = {0.0f, 0.0f};
        #pragma unroll
        for (int nt = 0; nt < 4; nt++) {
            int col = wc*32 + nt*8 + c2;
            float b0 = biasf[col], b1 = biasf[col + 1];
            #pragma unroll
            for (int h8 = 0; h8 < 2; h8++) {
                float f0 = acc[mt][nt][h8*2]     + b0;
                float f1 = acc[mt][nt][h8*2 + 1] + b1;
                if (RELU) { f0 = fmaxf(f0, 0.0f); f1 = fmaxf(f1, 0.0f); }
                __nv_bfloat162 p = __float22bfloat162_rn(make_float2(f0, f1));
                uint32_t pk = *(const uint32_t*)&p;
                int r = wr*32 + mt*16 + h8*8 + r8;
                int chunk = wc*4 + nt;
                uint32_t off = (uint32_t)outOff + (uint32_t)r*256
                             + (uint32_t)((chunk ^ (r & 7)) << 4) + (uint32_t)c2*2;
                *(uint32_t*)(smc + off) = pk;
                if (LAST) {
                    float2 fb = __bfloat1622float2(p);  // rounded-back values
                    srow[h8] += fb.x*fb.x + fb.y*fb.y;
                }
            }
        }
        if (LAST) {
            #pragma unroll
            for (int h8 = 0; h8 < 2; h8++) {
                float s = srow[h8];
                s += __shfl_xor_sync(0xffffffffu, s, 1);
                s += __shfl_xor_sync(0xffffffffu, s, 2);
                if ((lane & 3) == 0) {
                    int r = wr*32 + mt*16 + h8*8 + r8;
                    atomicAdd(&sq_sm[r], s);
                }
            }
        }
    }
}

__global__ void __launch_bounds__(256)
k_mlp(const float* __restrict__ b1, const float* __restrict__ b2,
      const float* __restrict__ b3) {
    extern __shared__ char smc[];
    float* biasf = (float*)smc;            // 512B
    float* sq_sm = (float*)(smc + 512);    // 256B
    float* red   = (float*)(smc + 768);    // 32B

    int tid = threadIdx.x, wid = tid >> 5, lane = tid & 31;
    int wr = wid & 1, wc = wid >> 1;
    int r0 = blockIdx.x * 64;

    uint4* Asm  = (uint4*)(smc + MLP_A);
    uint4* A2sm = (uint4*)(smc + MLP_A2);
    uint4* Wsm  = (uint4*)(smc + MLP_W);

    for (int e = tid; e < 1024; e += 256) Asm[e] = ((const uint4*)g_x)[r0*16 + e];
    for (int e = tid; e < 2048; e += 256) Wsm[e] = ((const uint4*)g_wt[0])[e];
    if (tid < DD) biasf[tid] = b1[tid];
    if (tid < 64) sq_sm[tid] = 0.0f;
    __syncthreads();

    float acc[2][4][4];

    // layer 1: A -> A2
    mlp_mma(smc, MLP_A, acc, lane, wr, wc);
    __syncthreads();
    mlp_store<true, false>(smc, MLP_A2, acc, biasf, sq_sm, lane, wr, wc);
    for (int e = tid; e < 2048; e += 256) Wsm[e] = ((const uint4*)g_wt[1])[e];
    __syncthreads();
    if (tid < DD) biasf[tid] = b2[tid];

    // layer 2: A2 -> A
    mlp_mma(smc, MLP_A2, acc, lane, wr, wc);
    __syncthreads();
    mlp_store<true, false>(smc, MLP_A, acc, biasf, sq_sm, lane, wr, wc);
    for (int e = tid; e < 2048; e += 256) Wsm[e] = ((const uint4*)g_wt[2])[e];
    __syncthreads();
    if (tid < DD) biasf[tid] = b3[tid];

    // layer 3: A -> A2 (no relu), with sq from rounded values
    mlp_mma(smc, MLP_A, acc, lane, wr, wc);
    __syncthreads();
    mlp_store<false, true>(smc, MLP_A2, acc, biasf, sq_sm, lane, wr, wc);
    __syncthreads();

    // copy rounded h out (already in swizzled-row layout)
    for (int e = tid; e < 1024; e += 256)
        ((uint4*)g_h)[r0*16 + e] = A2sm[e];

    if (tid < 64) {
        float sv = sq_sm[tid];
        g_sq[r0 + tid] = sv;
        sv += __shfl_xor_sync(0xffffffffu, sv, 16);
        sv += __shfl_xor_sync(0xffffffffu, sv, 8);
        sv += __shfl_xor_sync(0xffffffffu, sv, 4);
        sv += __shfl_xor_sync(0xffffffffu, sv, 2);
        sv += __shfl_xor_sync(0xffffffffu, sv, 1);
        if (lane == 0) red[wid] = sv;
    }
    __syncthreads();
    if (tid == 0) atomicAdd(&g_hsum, (double)(red[0] + red[1]));
}

// ---------------------------------------------------------------------------
// Pairwise via warp-level bf16 mma.sync: one 128x128 tile per CTA.
// g_h is pre-swizzled, so tile load is a linear uint4 copy. 8 warps in 4x2.
// Epilogue: cheap select; rare log path behind warp-uniform __any_sync.
// Last CTA (atomic ticket) finalizes the loss.
// ---------------------------------------------------------------------------
#define HI_OFF 4096
#define HJ_OFF (4096 + 32768)
#define PAIR_SMEM (4096 + 2*32768)

__global__ void __launch_bounds__(256, 2)
k_pair(const int* __restrict__ y, float* __restrict__ out) {
    extern __shared__ char smc[];
    float* redf = (float*)(smc + 16);
    float* sqi  = (float*)(smc + 64);
    float* sqj  = (float*)(smc + 576);
    int*   yi   = (int*)(smc + 1088);
    int*   yj   = (int*)(smc + 1600);
    char*  Hi   = smc + HI_OFF;
    char*  Hj   = smc + HJ_OFF;

    int tid = threadIdx.x, wid = tid >> 5, lane = tid & 31;

    // triangular tile mapping: block t -> (bi, bj) with bi <= bj
    int t = blockIdx.x;
    float nf = (float)NT + 0.5f;
    int bi = (int)(nf - sqrtf(nf*nf - 2.0f*(float)t));
    if (bi < 0) bi = 0;
    if (bi >= NT) bi = NT - 1;
    while (bi*NT - (bi*(bi-1))/2 > t) bi--;
    while ((bi+1)*NT - ((bi+1)*bi)/2 <= t) bi++;
    int bj = bi + (t - (bi*NT - (bi*(bi-1))/2));

    int ri = bi * 128, rj = bj * 128;

    // linear tile loads (g_h already swizzled)
    for (int e = tid; e < 2048; e += 256) {
        ((uint4*)Hi)[e] = ((const uint4*)g_h)[ri*16 + e];
        ((uint4*)Hj)[e] = ((const uint4*)g_h)[rj*16 + e];
    }
    if (tid < 128) {
        sqi[tid] = g_sq[ri + tid];
        sqj[tid] = g_sq[rj + tid];
        yi[tid]  = y[ri + tid];
        yj[tid]  = y[rj + tid];
    }
    __syncthreads();

    uint32_t hiB = smem_to_u32(Hi);
    uint32_t hjB = smem_to_u32(Hj);
    int wr = wid & 3, wc = wid >> 2;

    float acc[2][8][4];
    #pragma unroll
    for (int mt = 0; mt < 2; mt++)
        #pragma unroll
        for (int nt = 0; nt < 8; nt++)
            #pragma unroll
            for (int k = 0; k < 4; k++) acc[mt][nt][k] = 0.0f;

    int aRow0 = wr*32 + (lane & 15);
    int aSel  = lane >> 4;
    int bg    = lane >> 3;
    int bRow0 = wc*64 + ((bg >> 1) << 3) + (lane & 7);
    int bSel  = bg & 1;

    #pragma unroll 1
    for (int ks = 0; ks < 8; ks++) {
        uint32_t a[2][4];
        #pragma unroll
        for (int mt = 0; mt < 2; mt++) {
            int row = aRow0 + mt*16;
            uint32_t addr = hiB + (uint32_t)row*256
                          + (uint32_t)((((ks << 1) | aSel) ^ (row & 7)) << 4);
            ldm_x4(a[mt][0], a[mt][1], a[mt][2], a[mt][3], addr);
        }
        uint32_t b[8][2];
        #pragma unroll
        for (int np = 0; np < 4; np++) {
            int row = bRow0 + np*16;
            uint32_t addr = hjB + (uint32_t)row*256
                          + (uint32_t)((((ks << 1) | bSel) ^ (row & 7)) << 4);
            uint32_t r0, r1, r2, r3;
            ldm_x4(r0, r1, r2, r3, addr);
            b[2*np][0] = r0;   b[2*np][1] = r1;
            b[2*np+1][0] = r2; b[2*np+1][1] = r3;
        }
        #pragma unroll
        for (int mt = 0; mt < 2; mt++)
            #pragma unroll
            for (int nt = 0; nt < 8; nt++)
                mma_bf16(acc[mt][nt], a[mt], b[nt]);
    }

    // fused loss epilogue
    int r8 = lane >> 2, c2 = (lane & 3) << 1;
    float si[2][2]; int li[2][2];
    #pragma unroll
    for (int mt = 0; mt < 2; mt++)
        #pragma unroll
        for (int h = 0; h < 2; h++) {
            int row = wr*32 + mt*16 + h*8 + r8;
            si[mt][h] = sqi[row];
            li[mt][h] = yi[row];
        }
    float sj[8][2]; int lj[8][2];
    #pragma unroll
    for (int nt = 0; nt < 8; nt++)
        #pragma unroll
        for (int q = 0; q < 2; q++) {
            int col = wc*64 + nt*8 + c2 + q;
            sj[nt][q] = sqj[col];
            lj[nt][q] = yj[col];
        }

    float lsum = 0.0f;
    #pragma unroll
    for (int mt = 0; mt < 2; mt++)
        #pragma unroll
        for (int nt = 0; nt < 8; nt++) {
            #pragma unroll
            for (int h = 0; h < 2; h++)
                #pragma unroll
                for (int q = 0; q < 2; q++) {
                    float d = acc[mt][nt][h*2 + q];
                    float dist = fmaxf(si[mt][h] + sj[nt][q] - 2.0f*d, 0.0f);
                    bool  neq  = (li[mt][h] != lj[nt][q]);
                    float base = neq ? FARV : dist;
                    bool  rare = neq && (dist < 18.0f);
                    if (__any_sync(0xffffffffu, rare)) {
                        if (rare) base = -logf(1.01f - expf(-dist));
                    }
                    lsum += base;
                }
        }

    lsum += __shfl_xor_sync(0xffffffffu, lsum, 1);
    lsum += __shfl_xor_sync(0xffffffffu, lsum, 2);
    lsum += __shfl_xor_sync(0xffffffffu, lsum, 4);
    lsum += __shfl_xor_sync(0xffffffffu, lsum, 8);
    lsum += __shfl_xor_sync(0xffffffffu, lsum, 16);
    if (lane == 0) redf[wid] = lsum;
    __syncthreads();
    if (tid == 0) {
        double tot = 0.0;
        for (int w = 0; w < 8; w++) tot += (double)redf[w];
        if (bi != bj) tot *= 2.0;
        atomicAdd(&g_loss, tot);
        __threadfence();
        unsigned tk = atomicAdd(&g_ticket, 1u);
        if (tk == NBLK - 1) {
            __threadfence();
            double lt = atomicAdd(&g_loss, 0.0);
            double hs = atomicAdd(&g_hsum, 0.0);
            double loss = lt / ((double)BN * (double)BN);
            loss += 0.01 * (hs / ((double)BN * (double)DD));
            out[0] = (float)loss;
        }
    }
}

// ---------------------------------------------------------------------------

extern "C" void kernel_launch(void* const* d_in, const int* in_sizes, int n_in,
                              void* d_out, int out_size) {
    (void)in_sizes; (void)n_in; (void)out_size;
    const float* X  = (const float*)d_in[0];
    const float* W1 = (const float*)d_in[1];
    const float* b1 = (const float*)d_in[2];
    const float* W2 = (const float*)d_in[3];
    const float* b2 = (const float*)d_in[4];
    const float* W3 = (const float*)d_in[5];
    const float* b3 = (const float*)d_in[6];
    const int*   y  = (const int*)d_in[7];

    cudaFuncSetAttribute(k_mlp,  cudaFuncAttributeMaxDynamicSharedMemorySize, MLP_SMEM);
    cudaFuncSetAttribute(k_pair, cudaFuncAttributeMaxDynamicSharedMemorySize, PAIR_SMEM);

    k_prep<<<3 + 512, 256>>>(X, W1, W2, W3);
    k_mlp<<<BN/64, 256, MLP_SMEM>>>(b1, b2, b3);
    k_pair<<<NBLK, 256, PAIR_SMEM>>>(y, (float*)d_out);
}